// round 1
// baseline (speedup 1.0000x reference)
#include <cuda_runtime.h>

// Problem shape (fixed by the dataset)
#define NNODE  128          // nodes per graph
#define NEDGE  1024         // template edges per graph
#define ETOT   1152         // + 128 self loops
#define HFEAT  128
#define PITCH  129          // padded smem row pitch (floats)
#define NGRAPH 1024

// ---------------------------------------------------------------------------
// Device-global CSR (edge template shared by all graphs). Rebuilt every launch
// (deterministic), no allocations.
// ---------------------------------------------------------------------------
__device__ int g_csr_ptr[NNODE + 1];
__device__ int g_csr_src[ETOT];

__global__ void build_csr_kernel(const int* __restrict__ ei) {
    __shared__ int s_src[NEDGE];
    __shared__ int s_dst[NEDGE];
    __shared__ int cnt[NNODE];
    __shared__ int base[NNODE + 1];
    int t = threadIdx.x;
    if (t < NEDGE) { s_src[t] = ei[t]; s_dst[t] = ei[NEDGE + t]; }
    if (t < NNODE) cnt[t] = 0;
    __syncthreads();
    if (t < NEDGE) atomicAdd(&cnt[s_dst[t]], 1);
    __syncthreads();
    if (t == 0) {
        int acc = 0;
        for (int d = 0; d < NNODE; ++d) { base[d] = acc; acc += cnt[d] + 1; }
        base[NNODE] = acc;
    }
    __syncthreads();
    if (t <= NNODE) g_csr_ptr[t] = base[t];
    if (t < NEDGE) {
        // stable rank of edge t within its dst bucket (deterministic order,
        // matches reference concat order: edges first, self loop last)
        int d = s_dst[t];
        int rank = 0;
        for (int e = 0; e < t; ++e) rank += (s_dst[e] == d) ? 1 : 0;
        g_csr_src[base[d] + rank] = s_src[t];
    }
    if (t < NNODE) g_csr_src[base[t] + cnt[t]] = t;  // self loop appended last
}

// ---------------------------------------------------------------------------
// Shared-memory layout (per graph CTA)
// ---------------------------------------------------------------------------
// floats:
//   sh   : NNODE*PITCH   (16512)  node features (gemm input / layer output)
//   sxh  : NNODE*PITCH   (16512)  xh = h @ W
//   sex  : ETOT*4        (4608)   exp(e - max) per (edge, head)
//   s_s  : 512                     per-(node,head) src score
//   s_d  : 512                     per-(node,head) dst score
//   rinv : 512                     1 / softmax denominator
//   satt : 256                     a_s / a_d staged
//   hp   : 128                     pooled features
//   zz   : 64                      MLP hidden
// ints:
//   sptr : 132 (129 used, padded)
//   scsr : 1152
constexpr int SM_FLOATS = NNODE * PITCH * 2 + ETOT * 4 + 512 * 3 + 256 + 128 + 64;
constexpr int SM_INTS   = 132 + ETOT;
constexpr int SMEM_BYTES = SM_FLOATS * 4 + SM_INTS * 4;

// C[128,128] = A[128,128](smem, PITCH) @ W[128,128](global row-major)
// 256 threads, each computes an 8x8 register tile.
__device__ __forceinline__ void gemm128(const float* __restrict__ A,
                                        const float* __restrict__ W,
                                        float* __restrict__ C) {
    int tr = threadIdx.x >> 4;       // 0..15
    int tc = threadIdx.x & 15;       // 0..15
    int r0 = tr << 3, c0 = tc << 3;
    float acc[8][8];
#pragma unroll
    for (int i = 0; i < 8; ++i)
#pragma unroll
        for (int j = 0; j < 8; ++j) acc[i][j] = 0.0f;

#pragma unroll 4
    for (int k = 0; k < HFEAT; ++k) {
        float4 bv0 = *(const float4*)(W + k * HFEAT + c0);
        float4 bv1 = *(const float4*)(W + k * HFEAT + c0 + 4);
        float bb[8] = {bv0.x, bv0.y, bv0.z, bv0.w, bv1.x, bv1.y, bv1.z, bv1.w};
#pragma unroll
        for (int i = 0; i < 8; ++i) {
            float a = A[(r0 + i) * PITCH + k];
#pragma unroll
            for (int j = 0; j < 8; ++j) acc[i][j] = fmaf(a, bb[j], acc[i][j]);
        }
    }
#pragma unroll
    for (int i = 0; i < 8; ++i)
#pragma unroll
        for (int j = 0; j < 8; ++j)
            C[(r0 + i) * PITCH + c0 + j] = acc[i][j];
}

__global__ __launch_bounds__(256, 1)
void gnn_kernel(const float* __restrict__ x,
                const float* __restrict__ w_in, const float* __restrict__ b_in,
                const float* __restrict__ g0w, const float* __restrict__ g0as,
                const float* __restrict__ g0ad, const float* __restrict__ g0b,
                const float* __restrict__ bn0g, const float* __restrict__ bn0b,
                const float* __restrict__ bn0m, const float* __restrict__ bn0v,
                const float* __restrict__ g1w, const float* __restrict__ g1as,
                const float* __restrict__ g1ad, const float* __restrict__ g1b,
                const float* __restrict__ bn1g, const float* __restrict__ bn1b,
                const float* __restrict__ bn1m, const float* __restrict__ bn1v,
                const float* __restrict__ w1, const float* __restrict__ b1,
                const float* __restrict__ w2, const float* __restrict__ b2,
                float* __restrict__ out) {
    extern __shared__ float smem[];
    float* sh   = smem;
    float* sxh  = sh + NNODE * PITCH;
    float* sex  = sxh + NNODE * PITCH;
    float* s_s  = sex + ETOT * 4;
    float* s_d  = s_s + 512;
    float* rinv = s_d + 512;
    float* satt = rinv + 512;
    float* hp   = satt + 256;
    float* zz   = hp + 128;
    int*   sptr = (int*)(zz + 64);
    int*   scsr = sptr + 132;

    const int tid = threadIdx.x;
    const int b   = blockIdx.x;

    // stage CSR into smem
    for (int i = tid; i <= NNODE; i += 256) sptr[i] = g_csr_ptr[i];
    for (int i = tid; i < ETOT; i += 256)   scsr[i] = g_csr_src[i];

    // stage layer-0 attention vectors
    if (tid < 128) { satt[tid] = g0as[tid]; satt[128 + tid] = g0ad[tid]; }

    // -------- input projection: h = relu(x_n * w_in + b_in) --------
    const float* xr = x + b * NNODE;
    for (int it = tid; it < NNODE * HFEAT; it += 256) {
        int n = it >> 7, f = it & 127;
        float v = fmaf(xr[n], w_in[f], b_in[f]);
        sh[n * PITCH + f] = fmaxf(v, 0.0f);
    }
    __syncthreads();

    // ==================== GAT layer 0 (4 heads x 32) ====================
    gemm128(sh, g0w, sxh);
    __syncthreads();

    // per-(node, head) scores
    for (int it = tid; it < 512; it += 256) {
        int n = it >> 2, hh = it & 3;
        const float* row = &sxh[n * PITCH + hh * 32];
        const float* as = &satt[hh * 32];
        const float* ad = &satt[128 + hh * 32];
        float ssum = 0.0f, dsum = 0.0f;
#pragma unroll
        for (int k = 0; k < 32; ++k) {
            float v = row[k];
            ssum = fmaf(v, as[k], ssum);
            dsum = fmaf(v, ad[k], dsum);
        }
        s_s[n * 4 + hh] = ssum;
        s_d[n * 4 + hh] = dsum;
    }
    __syncthreads();

    // phase A: per (dst, head) softmax over incoming edges
    for (int it = tid; it < 512; it += 256) {
        int d = it >> 2, hh = it & 3;
        int beg = sptr[d], end = sptr[d + 1];
        float sd = s_d[d * 4 + hh];
        float mx = -1e30f;
        for (int p = beg; p < end; ++p) {
            float e = s_s[scsr[p] * 4 + hh] + sd;
            e = (e > 0.0f) ? e : 0.2f * e;
            mx = fmaxf(mx, e);
        }
        float sum = 0.0f;
        for (int p = beg; p < end; ++p) {
            float e = s_s[scsr[p] * 4 + hh] + sd;
            e = (e > 0.0f) ? e : 0.2f * e;
            float ex = __expf(e - mx);
            sex[p * 4 + hh] = ex;
            sum += ex;
        }
        rinv[d * 4 + hh] = 1.0f / sum;
    }
    __syncthreads();

    // phase B: aggregate + bias + BN0 + relu  -> sh
    for (int it = tid; it < NNODE * HFEAT; it += 256) {
        int d = it >> 7, f = it & 127, hh = f >> 5;
        int beg = sptr[d], end = sptr[d + 1];
        float acc = 0.0f;
        for (int p = beg; p < end; ++p)
            acc = fmaf(sex[p * 4 + hh], sxh[scsr[p] * PITCH + f], acc);
        acc = fmaf(acc, rinv[d * 4 + hh], g0b[f]);
        float scale = bn0g[f] * rsqrtf(bn0v[f] + 1e-5f);
        float v = fmaf(acc - bn0m[f], scale, bn0b[f]);
        sh[d * PITCH + f] = fmaxf(v, 0.0f);
    }
    __syncthreads();

    // ==================== GAT layer 1 (1 head x 128) ====================
    gemm128(sh, g1w, sxh);
    __syncthreads();

    if (tid < 128) { satt[tid] = g1as[tid]; satt[128 + tid] = g1ad[tid]; }
    __syncthreads();

    if (tid < 128) {
        const float* row = &sxh[tid * PITCH];
        float ssum = 0.0f, dsum = 0.0f;
#pragma unroll 4
        for (int k = 0; k < 128; ++k) {
            float v = row[k];
            ssum = fmaf(v, satt[k], ssum);
            dsum = fmaf(v, satt[128 + k], dsum);
        }
        s_s[tid] = ssum;
        s_d[tid] = dsum;
    }
    __syncthreads();

    if (tid < 128) {
        int d = tid;
        int beg = sptr[d], end = sptr[d + 1];
        float sd = s_d[d];
        float mx = -1e30f;
        for (int p = beg; p < end; ++p) {
            float e = s_s[scsr[p]] + sd;
            e = (e > 0.0f) ? e : 0.2f * e;
            mx = fmaxf(mx, e);
        }
        float sum = 0.0f;
        for (int p = beg; p < end; ++p) {
            float e = s_s[scsr[p]] + sd;
            e = (e > 0.0f) ? e : 0.2f * e;
            float ex = __expf(e - mx);
            sex[p] = ex;
            sum += ex;
        }
        rinv[d] = 1.0f / sum;
    }
    __syncthreads();

    for (int it = tid; it < NNODE * HFEAT; it += 256) {
        int d = it >> 7, f = it & 127;
        int beg = sptr[d], end = sptr[d + 1];
        float acc = 0.0f;
        for (int p = beg; p < end; ++p)
            acc = fmaf(sex[p], sxh[scsr[p] * PITCH + f], acc);
        acc = fmaf(acc, rinv[d], g1b[f]);
        float scale = bn1g[f] * rsqrtf(bn1v[f] + 1e-5f);
        float v = fmaf(acc - bn1m[f], scale, bn1b[f]);
        sh[d * PITCH + f] = fmaxf(v, 0.0f);
    }
    __syncthreads();

    // -------- mean pool + MLP --------
    if (tid < 128) {
        float acc = 0.0f;
#pragma unroll 4
        for (int n = 0; n < NNODE; ++n) acc += sh[n * PITCH + tid];
        hp[tid] = acc * (1.0f / 128.0f);
    }
    __syncthreads();

    if (tid < 64) {
        float acc = b1[tid];
#pragma unroll 4
        for (int f = 0; f < 128; ++f) acc = fmaf(hp[f], w1[f * 64 + tid], acc);
        zz[tid] = fmaxf(acc, 0.0f);
    }
    __syncthreads();

    if (tid == 0) {
        float acc = b2[0];
#pragma unroll
        for (int j = 0; j < 64; ++j) acc = fmaf(zz[j], w2[j], acc);
        out[b] = acc;
    }
}

// ---------------------------------------------------------------------------
extern "C" void kernel_launch(void* const* d_in, const int* in_sizes, int n_in,
                              void* d_out, int out_size) {
    (void)in_sizes; (void)n_in; (void)out_size;
    const float* x    = (const float*)d_in[0];
    const int*   ei   = (const int*)d_in[1];
    const float* w_in = (const float*)d_in[2];
    const float* b_in = (const float*)d_in[3];
    const float* g0w  = (const float*)d_in[4];
    const float* g0as = (const float*)d_in[5];
    const float* g0ad = (const float*)d_in[6];
    const float* g0b  = (const float*)d_in[7];
    const float* bn0g = (const float*)d_in[8];
    const float* bn0b = (const float*)d_in[9];
    const float* bn0m = (const float*)d_in[10];
    const float* bn0v = (const float*)d_in[11];
    const float* g1w  = (const float*)d_in[12];
    const float* g1as = (const float*)d_in[13];
    const float* g1ad = (const float*)d_in[14];
    const float* g1b  = (const float*)d_in[15];
    const float* bn1g = (const float*)d_in[16];
    const float* bn1b = (const float*)d_in[17];
    const float* bn1m = (const float*)d_in[18];
    const float* bn1v = (const float*)d_in[19];
    const float* w1   = (const float*)d_in[20];
    const float* b1   = (const float*)d_in[21];
    const float* w2   = (const float*)d_in[22];
    const float* b2   = (const float*)d_in[23];
    float* out = (float*)d_out;

    cudaFuncSetAttribute(gnn_kernel,
                         cudaFuncAttributeMaxDynamicSharedMemorySize, SMEM_BYTES);

    build_csr_kernel<<<1, 1024>>>(ei);
    gnn_kernel<<<NGRAPH, 256, SMEM_BYTES>>>(
        x, w_in, b_in,
        g0w, g0as, g0ad, g0b, bn0g, bn0b, bn0m, bn0v,
        g1w, g1as, g1ad, g1b, bn1g, bn1b, bn1m, bn1v,
        w1, b1, w2, b2, out);
}

// round 2
// speedup vs baseline: 1.3772x; 1.3772x over previous
#include <cuda_runtime.h>

#define NNODE  128
#define NEDGE  1024
#define ETOT   1152
#define HFEAT  128
#define PITCH  132          // float4-aligned padded pitch
#define NGRAPH 1024
#define NTHREADS 512

// ---------------------------------------------------------------------------
// Device-global CSR (edge template shared by all graphs).
// ---------------------------------------------------------------------------
__device__ int g_csr_ptr[NNODE + 1];
__device__ int g_csr_src[ETOT];

__global__ void build_csr_kernel(const int* __restrict__ ei) {
    __shared__ int s_src[NEDGE];
    __shared__ int s_dst[NEDGE];
    __shared__ int cnt[NNODE];
    __shared__ int base[NNODE + 1];
    int t = threadIdx.x;
    if (t < NEDGE) { s_src[t] = ei[t]; s_dst[t] = ei[NEDGE + t]; }
    if (t < NNODE) cnt[t] = 0;
    __syncthreads();
    if (t < NEDGE) atomicAdd(&cnt[s_dst[t]], 1);
    __syncthreads();
    if (t == 0) {
        int acc = 0;
        for (int d = 0; d < NNODE; ++d) { base[d] = acc; acc += cnt[d] + 1; }
        base[NNODE] = acc;
    }
    __syncthreads();
    if (t <= NNODE) g_csr_ptr[t] = base[t];
    if (t < NEDGE) {
        // stable rank within dst bucket (deterministic, matches reference order)
        int d = s_dst[t];
        int rank = 0;
        for (int e = 0; e < t; ++e) rank += (s_dst[e] == d) ? 1 : 0;
        g_csr_src[base[d] + rank] = s_src[t];
    }
    if (t < NNODE) g_csr_src[base[t] + cnt[t]] = t;  // self loop last
}

// ---------------------------------------------------------------------------
// Shared memory layout
// ---------------------------------------------------------------------------
constexpr int OFF_SH    = 0;
constexpr int OFF_SXH   = OFF_SH  + NNODE * PITCH;       // 16896
constexpr int OFF_SEX   = OFF_SXH + NNODE * PITCH;
constexpr int OFF_SS    = OFF_SEX + ETOT * 4;
constexpr int OFF_SD    = OFF_SS  + 512;
constexpr int OFF_RINV  = OFF_SD  + 512;
constexpr int OFF_SATT  = OFF_RINV + 512;                // 256
constexpr int OFF_SCALE = OFF_SATT + 256;                // 128
constexpr int OFF_BIAS  = OFF_SCALE + 128;               // 128
constexpr int OFF_POOL  = OFF_BIAS + 128;                // 512
constexpr int OFF_HP    = OFF_POOL + 512;                // 128
constexpr int OFF_ZZ    = OFF_HP + 128;                  // 64
constexpr int SM_FLOATS = OFF_ZZ + 64;
constexpr int SM_INTS   = 132 + ETOT;
constexpr int SMEM_BYTES = SM_FLOATS * 4 + SM_INTS * 4;

// C[128,128] = A(smem, PITCH) @ W(global row-major). 512 threads, 4x8 tiles.
__device__ __forceinline__ void gemm128(const float* __restrict__ A,
                                        const float* __restrict__ W,
                                        float* __restrict__ C, int tid) {
    const int r0 = (tid >> 4) << 2;   // 0..124
    const int c0 = (tid & 15) << 3;   // 0..120
    float acc[4][8];
#pragma unroll
    for (int i = 0; i < 4; ++i)
#pragma unroll
        for (int j = 0; j < 8; ++j) acc[i][j] = 0.0f;

#pragma unroll 2
    for (int k0 = 0; k0 < HFEAT; k0 += 4) {
        float4 a[4];
#pragma unroll
        for (int i = 0; i < 4; ++i)
            a[i] = *(const float4*)(A + (r0 + i) * PITCH + k0);
        float4 wv[8];
#pragma unroll
        for (int kk = 0; kk < 4; ++kk) {
            wv[2 * kk]     = *(const float4*)(W + (k0 + kk) * HFEAT + c0);
            wv[2 * kk + 1] = *(const float4*)(W + (k0 + kk) * HFEAT + c0 + 4);
        }
#pragma unroll
        for (int kk = 0; kk < 4; ++kk) {
            float bb[8] = {wv[2*kk].x, wv[2*kk].y, wv[2*kk].z, wv[2*kk].w,
                           wv[2*kk+1].x, wv[2*kk+1].y, wv[2*kk+1].z, wv[2*kk+1].w};
#pragma unroll
            for (int i = 0; i < 4; ++i) {
                float av = (kk == 0) ? a[i].x : (kk == 1) ? a[i].y
                         : (kk == 2) ? a[i].z : a[i].w;
#pragma unroll
                for (int j = 0; j < 8; ++j)
                    acc[i][j] = fmaf(av, bb[j], acc[i][j]);
            }
        }
    }
#pragma unroll
    for (int i = 0; i < 4; ++i) {
        *(float4*)(C + (r0 + i) * PITCH + c0)     =
            make_float4(acc[i][0], acc[i][1], acc[i][2], acc[i][3]);
        *(float4*)(C + (r0 + i) * PITCH + c0 + 4) =
            make_float4(acc[i][4], acc[i][5], acc[i][6], acc[i][7]);
    }
}

__global__ __launch_bounds__(NTHREADS, 1)
void gnn_kernel(const float* __restrict__ x,
                const float* __restrict__ w_in, const float* __restrict__ b_in,
                const float* __restrict__ g0w, const float* __restrict__ g0as,
                const float* __restrict__ g0ad, const float* __restrict__ g0b,
                const float* __restrict__ bn0g, const float* __restrict__ bn0b,
                const float* __restrict__ bn0m, const float* __restrict__ bn0v,
                const float* __restrict__ g1w, const float* __restrict__ g1as,
                const float* __restrict__ g1ad, const float* __restrict__ g1b,
                const float* __restrict__ bn1g, const float* __restrict__ bn1b,
                const float* __restrict__ bn1m, const float* __restrict__ bn1v,
                const float* __restrict__ w1, const float* __restrict__ b1,
                const float* __restrict__ w2, const float* __restrict__ b2,
                float* __restrict__ out) {
    extern __shared__ float smem[];
    float* sh    = smem + OFF_SH;
    float* sxh   = smem + OFF_SXH;
    float* sex   = smem + OFF_SEX;
    float* s_s   = smem + OFF_SS;
    float* s_d   = smem + OFF_SD;
    float* rinv  = smem + OFF_RINV;
    float* satt  = smem + OFF_SATT;
    float* sscale= smem + OFF_SCALE;
    float* sbias = smem + OFF_BIAS;
    float* pool  = smem + OFF_POOL;
    float* hp    = smem + OFF_HP;
    float* zz    = smem + OFF_ZZ;
    int*   sptr  = (int*)(smem + SM_FLOATS);
    int*   scsr  = sptr + 132;

    const int tid  = threadIdx.x;
    const int wid  = tid >> 5;
    const int lane = tid & 31;
    const int b    = blockIdx.x;

    // stage CSR
    for (int i = tid; i <= NNODE; i += NTHREADS) sptr[i] = g_csr_ptr[i];
    for (int i = tid; i < ETOT; i += NTHREADS)   scsr[i] = g_csr_src[i];

    // stage layer-0 attention + BN0 fold:  out = agg*rinv*scale + bias_tot
    if (tid < 128) {
        satt[tid]       = g0as[tid];
        satt[128 + tid] = g0ad[tid];
        float sc = bn0g[tid] * rsqrtf(bn0v[tid] + 1e-5f);
        sscale[tid] = sc;
        sbias[tid]  = fmaf(g0b[tid] - bn0m[tid], sc, bn0b[tid]);
    }

    // -------- input projection (vectorized) --------
    const float* xr = x + b * NNODE;
    for (int it = tid; it < NNODE * 32; it += NTHREADS) {
        int n = it >> 5, fq = it & 31;
        float xv = xr[n];
        float4 w = *(const float4*)(w_in + fq * 4);
        float4 bb = *(const float4*)(b_in + fq * 4);
        float4 r;
        r.x = fmaxf(fmaf(xv, w.x, bb.x), 0.0f);
        r.y = fmaxf(fmaf(xv, w.y, bb.y), 0.0f);
        r.z = fmaxf(fmaf(xv, w.z, bb.z), 0.0f);
        r.w = fmaxf(fmaf(xv, w.w, bb.w), 0.0f);
        *(float4*)(sh + n * PITCH + fq * 4) = r;
    }
    __syncthreads();

    // ==================== GAT layer 0 ====================
    gemm128(sh, g0w, sxh, tid);
    __syncthreads();

    // per-(node, head) scores: item = (hh, n), lanes span consecutive n
    {
        int n  = tid & 127;
        int hh = tid >> 7;
        const float* row = &sxh[n * PITCH + hh * 32];
        const float* as  = &satt[hh * 32];
        const float* ad  = &satt[128 + hh * 32];
        float ssum = 0.0f, dsum = 0.0f;
#pragma unroll
        for (int q = 0; q < 8; ++q) {
            float4 v  = *(const float4*)(row + q * 4);
            float4 a1 = *(const float4*)(as + q * 4);
            float4 a2 = *(const float4*)(ad + q * 4);
            ssum = fmaf(v.x, a1.x, fmaf(v.y, a1.y, fmaf(v.z, a1.z, fmaf(v.w, a1.w, ssum))));
            dsum = fmaf(v.x, a2.x, fmaf(v.y, a2.y, fmaf(v.z, a2.z, fmaf(v.w, a2.w, dsum))));
        }
        s_s[n * 4 + hh] = ssum;
        s_d[n * 4 + hh] = dsum;
    }
    __syncthreads();

    // softmax per (dst, head)
    {
        int d  = tid & 127;
        int hh = tid >> 7;
        int beg = sptr[d], end = sptr[d + 1];
        float sd = s_d[d * 4 + hh];
        float mx = -1e30f;
        for (int p = beg; p < end; ++p) {
            float e = s_s[scsr[p] * 4 + hh] + sd;
            e = (e > 0.0f) ? e : 0.2f * e;
            mx = fmaxf(mx, e);
        }
        float sum = 0.0f;
        for (int p = beg; p < end; ++p) {
            float e = s_s[scsr[p] * 4 + hh] + sd;
            e = (e > 0.0f) ? e : 0.2f * e;
            float ex = __expf(e - mx);
            sex[p * 4 + hh] = ex;
            sum += ex;
        }
        rinv[d * 4 + hh] = 1.0f / sum;
    }
    __syncthreads();

    // aggregate + BN0 + relu (warp-per-node, float4 per lane) -> sh
    {
        int hh = lane >> 3;
        float4 sc = *(const float4*)(sscale + lane * 4);
        float4 bs = *(const float4*)(sbias + lane * 4);
        for (int d = wid; d < NNODE; d += 16) {
            int beg = sptr[d], end = sptr[d + 1];
            float rv = rinv[d * 4 + hh];
            float4 acc = make_float4(0.f, 0.f, 0.f, 0.f);
            for (int p = beg; p < end; ++p) {
                float w = sex[p * 4 + hh];
                const float4 v = *(const float4*)(sxh + scsr[p] * PITCH + lane * 4);
                acc.x = fmaf(w, v.x, acc.x);
                acc.y = fmaf(w, v.y, acc.y);
                acc.z = fmaf(w, v.z, acc.z);
                acc.w = fmaf(w, v.w, acc.w);
            }
            float4 r;
            r.x = fmaxf(fmaf(acc.x * rv, sc.x, bs.x), 0.0f);
            r.y = fmaxf(fmaf(acc.y * rv, sc.y, bs.y), 0.0f);
            r.z = fmaxf(fmaf(acc.z * rv, sc.z, bs.z), 0.0f);
            r.w = fmaxf(fmaf(acc.w * rv, sc.w, bs.w), 0.0f);
            *(float4*)(sh + d * PITCH + lane * 4) = r;
        }
    }
    // stage layer-1 attention + BN1 fold (used only after next sync)
    if (tid < 128) {
        float sc = bn1g[tid] * rsqrtf(bn1v[tid] + 1e-5f);
        sscale[tid] = sc;
        sbias[tid]  = fmaf(g1b[tid] - bn1m[tid], sc, bn1b[tid]);
        satt[tid]       = g1as[tid];
        satt[128 + tid] = g1ad[tid];
    }
    __syncthreads();

    // ==================== GAT layer 1 ====================
    gemm128(sh, g1w, sxh, tid);
    __syncthreads();

    // scores: warp per node, shuffle reduce
    {
        float4 a1 = *(const float4*)(satt + lane * 4);
        float4 a2 = *(const float4*)(satt + 128 + lane * 4);
        for (int nd = wid; nd < NNODE; nd += 16) {
            float4 v = *(const float4*)(sxh + nd * PITCH + lane * 4);
            float ss = v.x*a1.x + v.y*a1.y + v.z*a1.z + v.w*a1.w;
            float dd = v.x*a2.x + v.y*a2.y + v.z*a2.z + v.w*a2.w;
#pragma unroll
            for (int o = 16; o; o >>= 1) {
                ss += __shfl_xor_sync(0xffffffffu, ss, o);
                dd += __shfl_xor_sync(0xffffffffu, dd, o);
            }
            if (lane == 0) { s_s[nd] = ss; s_d[nd] = dd; }
        }
    }
    __syncthreads();

    if (tid < 128) {
        int d = tid;
        int beg = sptr[d], end = sptr[d + 1];
        float sd = s_d[d];
        float mx = -1e30f;
        for (int p = beg; p < end; ++p) {
            float e = s_s[scsr[p]] + sd;
            e = (e > 0.0f) ? e : 0.2f * e;
            mx = fmaxf(mx, e);
        }
        float sum = 0.0f;
        for (int p = beg; p < end; ++p) {
            float e = s_s[scsr[p]] + sd;
            e = (e > 0.0f) ? e : 0.2f * e;
            float ex = __expf(e - mx);
            sex[p] = ex;
            sum += ex;
        }
        rinv[d] = 1.0f / sum;
    }
    __syncthreads();

    // aggregate + BN1 + relu -> sh
    {
        float4 sc = *(const float4*)(sscale + lane * 4);
        float4 bs = *(const float4*)(sbias + lane * 4);
        for (int d = wid; d < NNODE; d += 16) {
            int beg = sptr[d], end = sptr[d + 1];
            float rv = rinv[d];
            float4 acc = make_float4(0.f, 0.f, 0.f, 0.f);
            for (int p = beg; p < end; ++p) {
                float w = sex[p];
                const float4 v = *(const float4*)(sxh + scsr[p] * PITCH + lane * 4);
                acc.x = fmaf(w, v.x, acc.x);
                acc.y = fmaf(w, v.y, acc.y);
                acc.z = fmaf(w, v.z, acc.z);
                acc.w = fmaf(w, v.w, acc.w);
            }
            float4 r;
            r.x = fmaxf(fmaf(acc.x * rv, sc.x, bs.x), 0.0f);
            r.y = fmaxf(fmaf(acc.y * rv, sc.y, bs.y), 0.0f);
            r.z = fmaxf(fmaf(acc.z * rv, sc.z, bs.z), 0.0f);
            r.w = fmaxf(fmaf(acc.w * rv, sc.w, bs.w), 0.0f);
            *(float4*)(sh + d * PITCH + lane * 4) = r;
        }
    }
    __syncthreads();

    // -------- mean pool (4 partial groups) --------
    {
        int g = tid >> 7, f = tid & 127;
        float acc = 0.0f;
#pragma unroll 4
        for (int n = g * 32; n < g * 32 + 32; ++n) acc += sh[n * PITCH + f];
        pool[g * 128 + f] = acc;
    }
    __syncthreads();
    if (tid < 128)
        hp[tid] = (pool[tid] + pool[128 + tid] + pool[256 + tid] + pool[384 + tid])
                  * (1.0f / 128.0f);
    __syncthreads();

    // -------- MLP --------
    if (tid < 64) {
        float acc = b1[tid];
#pragma unroll 8
        for (int f = 0; f < 128; ++f) acc = fmaf(hp[f], w1[f * 64 + tid], acc);
        zz[tid] = fmaxf(acc, 0.0f);
    }
    __syncthreads();
    if (tid == 0) {
        float acc = b2[0];
#pragma unroll
        for (int j = 0; j < 64; ++j) acc = fmaf(zz[j], w2[j], acc);
        out[b] = acc;
    }
}

// ---------------------------------------------------------------------------
extern "C" void kernel_launch(void* const* d_in, const int* in_sizes, int n_in,
                              void* d_out, int out_size) {
    (void)in_sizes; (void)n_in; (void)out_size;
    const float* x    = (const float*)d_in[0];
    const int*   ei   = (const int*)d_in[1];
    const float* w_in = (const float*)d_in[2];
    const float* b_in = (const float*)d_in[3];
    const float* g0w  = (const float*)d_in[4];
    const float* g0as = (const float*)d_in[5];
    const float* g0ad = (const float*)d_in[6];
    const float* g0b  = (const float*)d_in[7];
    const float* bn0g = (const float*)d_in[8];
    const float* bn0b = (const float*)d_in[9];
    const float* bn0m = (const float*)d_in[10];
    const float* bn0v = (const float*)d_in[11];
    const float* g1w  = (const float*)d_in[12];
    const float* g1as = (const float*)d_in[13];
    const float* g1ad = (const float*)d_in[14];
    const float* g1b  = (const float*)d_in[15];
    const float* bn1g = (const float*)d_in[16];
    const float* bn1b = (const float*)d_in[17];
    const float* bn1m = (const float*)d_in[18];
    const float* bn1v = (const float*)d_in[19];
    const float* w1   = (const float*)d_in[20];
    const float* b1   = (const float*)d_in[21];
    const float* w2   = (const float*)d_in[22];
    const float* b2   = (const float*)d_in[23];
    float* out = (float*)d_out;

    cudaFuncSetAttribute(gnn_kernel,
                         cudaFuncAttributeMaxDynamicSharedMemorySize, SMEM_BYTES);

    build_csr_kernel<<<1, 1024>>>(ei);
    gnn_kernel<<<NGRAPH, NTHREADS, SMEM_BYTES>>>(
        x, w_in, b_in,
        g0w, g0as, g0ad, g0b, bn0g, bn0b, bn0m, bn0v,
        g1w, g1as, g1ad, g1b, bn1g, bn1b, bn1m, bn1v,
        w1, b1, w2, b2, out);
}